// round 8
// baseline (speedup 1.0000x reference)
#include <cuda_runtime.h>
#include <math.h>
#include <stdint.h>

#define HID   768
#define BATCH 4
#define SEQ   2048
#define NH    12
#define HD    64
#define NEG_BIG (-1e31f)

// Scratch Q,K,V in [B,H,S,hd] layout (device globals: allocation-free)
__device__ float g_q[BATCH*NH*SEQ*HD];
__device__ float g_k[BATCH*NH*SEQ*HD];
__device__ float g_v[BATCH*NH*SEQ*HD];

// ---------------------------------------------------------------------------
// helpers
// ---------------------------------------------------------------------------
__device__ __forceinline__ uint32_t f2tf(float f) {
    uint32_t u;
    asm("cvt.rna.tf32.f32 %0, %1;" : "=r"(u) : "f"(f));
    return u;
}

__device__ __forceinline__ void mma_tf32(float* c, const uint32_t* a,
                                         uint32_t b0, uint32_t b1) {
    asm volatile(
        "mma.sync.aligned.m16n8k8.row.col.f32.tf32.tf32.f32 "
        "{%0,%1,%2,%3},{%4,%5,%6,%7},{%8,%9},{%0,%1,%2,%3};"
        : "+f"(c[0]), "+f"(c[1]), "+f"(c[2]), "+f"(c[3])
        : "r"(a[0]), "r"(a[1]), "r"(a[2]), "r"(a[3]), "r"(b0), "r"(b1));
}

__device__ __forceinline__ uint4 tf4(float4 v) {
    uint4 u;
    u.x = f2tf(v.x); u.y = f2tf(v.y); u.z = f2tf(v.z); u.w = f2tf(v.w);
    return u;
}

// ---------------------------------------------------------------------------
// Kernel 1: fused QKV projection with tf32 tensor cores.
// C[8192,2304] = toks @ [Wq|Wk|Wv] + bias -> permuted into g_q/g_k/g_v [B,H,S,hd]
// Block tile 128x128, K-tile 32.  256 threads = 8 warps (4 M x 2 N),
// warp tile 32x64 -> 2 m-blocks x 8 n-blocks of m16n8k8.
// ---------------------------------------------------------------------------
#define ASTR 36
#define BSTR 136
__global__ __launch_bounds__(256) void qkv_gemm_kernel(
        const float* __restrict__ toks,
        const float* __restrict__ Wq, const float* __restrict__ bq,
        const float* __restrict__ Wk, const float* __restrict__ bk,
        const float* __restrict__ Wv, const float* __restrict__ bv) {
    __shared__ float sA[128 * ASTR];   // [m][k] stride 36
    __shared__ float sB[32 * BSTR];    // [k][n] stride 136

    const int nbk = blockIdx.x;        // 0..17
    const int mb  = blockIdx.y;        // 0..63
    const int tid = threadIdx.x;
    const int warpId = tid >> 5;
    const int lane = tid & 31;
    const int g   = lane >> 2;
    const int tig = lane & 3;
    const int wm  = warpId >> 1;       // 0..3
    const int wn  = warpId & 1;        // 0..1

    const int w  = (nbk * 128) / HID;        // which of Q/K/V
    const int nc = (nbk * 128) % HID;
    const float* __restrict__ Wsel = (w == 0) ? Wq : (w == 1) ? Wk : Wv;
    const float* __restrict__ bsel = (w == 0) ? bq : (w == 1) ? bk : bv;

    float acc[2][8][4];
#pragma unroll
    for (int mi = 0; mi < 2; mi++)
#pragma unroll
        for (int nb = 0; nb < 8; nb++)
#pragma unroll
            for (int j = 0; j < 4; j++) acc[mi][nb][j] = 0.f;

    for (int k0 = 0; k0 < HID; k0 += 32) {
#pragma unroll
        for (int i = 0; i < 4; i++) {
            int idx = tid + i * 256;           // 0..1023
            int r = idx >> 3, cg = idx & 7;
            float4 a = *(const float4*)&toks[(size_t)(mb * 128 + r) * HID + k0 + cg * 4];
            *(uint4*)&sA[r * ASTR + cg * 4] = tf4(a);
        }
#pragma unroll
        for (int i = 0; i < 4; i++) {
            int idx = tid + i * 256;
            int r = idx >> 5, cg = idx & 31;
            float4 bvv = *(const float4*)&Wsel[(size_t)(k0 + r) * HID + nc + cg * 4];
            *(uint4*)&sB[r * BSTR + cg * 4] = tf4(bvv);
        }
        __syncthreads();

#pragma unroll
        for (int kc = 0; kc < 4; kc++) {
            uint32_t af[2][4];
#pragma unroll
            for (int mi = 0; mi < 2; mi++) {
                int row = wm * 32 + mi * 16;
                af[mi][0] = __float_as_uint(sA[(row + g)     * ASTR + kc * 8 + tig]);
                af[mi][1] = __float_as_uint(sA[(row + g + 8) * ASTR + kc * 8 + tig]);
                af[mi][2] = __float_as_uint(sA[(row + g)     * ASTR + kc * 8 + tig + 4]);
                af[mi][3] = __float_as_uint(sA[(row + g + 8) * ASTR + kc * 8 + tig + 4]);
            }
            uint32_t bf[8][2];
#pragma unroll
            for (int nb = 0; nb < 8; nb++) {
                int col = wn * 64 + nb * 8 + g;
                bf[nb][0] = __float_as_uint(sB[(kc * 8 + tig)     * BSTR + col]);
                bf[nb][1] = __float_as_uint(sB[(kc * 8 + tig + 4) * BSTR + col]);
            }
#pragma unroll
            for (int mi = 0; mi < 2; mi++)
#pragma unroll
                for (int nb = 0; nb < 8; nb++)
                    mma_tf32(acc[mi][nb], af[mi], bf[nb][0], bf[nb][1]);
        }
        __syncthreads();
    }

    float* __restrict__ buf = (w == 0) ? g_q : (w == 1) ? g_k : g_v;
#pragma unroll
    for (int mi = 0; mi < 2; mi++) {
#pragma unroll
        for (int nb = 0; nb < 8; nb++) {
            int n = nc + wn * 64 + nb * 8 + 2 * tig;
            int h = n >> 6;
            int d = n & 63;
            float b0v = bsel[n], b1v = bsel[n + 1];
            int row = mb * 128 + wm * 32 + mi * 16 + g;
            int bb = row >> 11;
            int ss = row & 2047;
            float* dst = &buf[((size_t)(bb * NH + h) * SEQ + ss) * HD + d];
            *(float2*)dst = make_float2(acc[mi][nb][0] + b0v, acc[mi][nb][1] + b1v);
            *(float2*)(dst + 8 * HD) = make_float2(acc[mi][nb][2] + b0v,
                                                   acc[mi][nb][3] + b1v);
        }
    }
}

// ---------------------------------------------------------------------------
// Kernel 2: flash attention, tf32 mma, 32 q-rows per warp (2 m-blocks).
// Grid (16 q-tiles of 128 rows, 12 heads, 4 batch), 128 threads = 4 warps.
// B fragments (K and V) are reused across both m-blocks -> ~0.6x smem
// wavefronts per FMA vs round 2.  P staged per-warp in two 32-key halves
// (32x36 buffer) with __syncwarp ordering only.
// ---------------------------------------------------------------------------
#define KSTR 68
#define VSTR 72
#define PSTR 36
__global__ __launch_bounds__(128) void attn_kernel(const int* __restrict__ masks,
                                                   float* __restrict__ out) {
    __shared__ float sKV[64 * VSTR];        // K phase (stride 68), V phase (stride 72)
    __shared__ float sP[4 * 32 * PSTR];     // per-warp 32x32 P half-tiles
    __shared__ float sMk[64];

    const int qt  = blockIdx.x;             // 0..15 (128 q rows each)
    const int h   = blockIdx.y;
    const int b   = blockIdx.z;
    const int tid = threadIdx.x;
    const int w    = tid >> 5;
    const int lane = tid & 31;
    const int g    = lane >> 2;
    const int tig  = lane & 3;

    const size_t bh = (size_t)(b * NH + h) * SEQ;
    const float* __restrict__ Qb = g_q + (bh + qt * 128 + w * 32) * HD;
    const float* __restrict__ Kb = g_k + bh * HD;
    const float* __restrict__ Vb = g_v + bh * HD;
    const int*   __restrict__ mrow = masks + b * SEQ;

    // register-resident Q fragments: 2 m-blocks x 8 k-chunks x 4 regs
    uint32_t qa[2][8][4];
#pragma unroll
    for (int mi = 0; mi < 2; mi++)
#pragma unroll
        for (int kc = 0; kc < 8; kc++) {
            int r0 = mi * 16 + g;
            qa[mi][kc][0] = f2tf(Qb[(size_t)r0 * HD + kc * 8 + tig]);
            qa[mi][kc][1] = f2tf(Qb[(size_t)(r0 + 8) * HD + kc * 8 + tig]);
            qa[mi][kc][2] = f2tf(Qb[(size_t)r0 * HD + kc * 8 + tig + 4]);
            qa[mi][kc][3] = f2tf(Qb[(size_t)(r0 + 8) * HD + kc * 8 + tig + 4]);
        }
    float fq[2][2];
#pragma unroll
    for (int mi = 0; mi < 2; mi++) {
        fq[mi][0] = (float)mrow[qt * 128 + w * 32 + mi * 16 + g];
        fq[mi][1] = (float)mrow[qt * 128 + w * 32 + mi * 16 + g + 8];
    }

    float o[2][8][4];
    float mm[2][2], ll[2][2];
#pragma unroll
    for (int mi = 0; mi < 2; mi++) {
        mm[mi][0] = mm[mi][1] = -3.0e38f;
        ll[mi][0] = ll[mi][1] = 0.f;
#pragma unroll
        for (int nb = 0; nb < 8; nb++)
#pragma unroll
            for (int j = 0; j < 4; j++) o[mi][nb][j] = 0.f;
    }

    float* Pw = sP + w * 32 * PSTR;

    for (int t = 0; t < SEQ / 64; t++) {
        __syncthreads();                    // prev V reads done
        // stage K tile [key][dim], stride 68, tf32
#pragma unroll
        for (int i = 0; i < 8; i++) {
            int idx = tid + i * 128;
            int r = idx >> 4, cg = idx & 15;
            float4 kv = *(const float4*)&Kb[(size_t)(t * 64 + r) * HD + cg * 4];
            *(uint4*)&sKV[r * KSTR + cg * 4] = tf4(kv);
        }
        if (tid < 64) sMk[tid] = (float)mrow[t * 64 + tid];
        __syncthreads();

        // S = Q K^T : 2 m-blocks share each B fragment
        float sacc[2][8][4];
#pragma unroll
        for (int nb = 0; nb < 8; nb++) {
            float c0[4] = {0.f, 0.f, 0.f, 0.f};
            float c1[4] = {0.f, 0.f, 0.f, 0.f};
#pragma unroll
            for (int kc = 0; kc < 8; kc++) {
                uint32_t b0 = __float_as_uint(sKV[(nb * 8 + g) * KSTR + kc * 8 + tig]);
                uint32_t b1 = __float_as_uint(sKV[(nb * 8 + g) * KSTR + kc * 8 + tig + 4]);
                mma_tf32(c0, qa[0][kc], b0, b1);
                mma_tf32(c1, qa[1][kc], b0, b1);
            }
#pragma unroll
            for (int j = 0; j < 4; j++) { sacc[0][nb][j] = c0[j]; sacc[1][nb][j] = c1[j]; }
        }

        // scale + mask + online softmax (per m-block, per row-half)
#pragma unroll
        for (int mi = 0; mi < 2; mi++) {
            float mx0 = -3.0e38f, mx1 = -3.0e38f;
#pragma unroll
            for (int nb = 0; nb < 8; nb++) {
#pragma unroll
                for (int j = 0; j < 2; j++) {
                    float fk = sMk[nb * 8 + 2 * tig + j];
                    float s0 = sacc[mi][nb][j]     * 0.125f + (1.0f - fq[mi][0] * fk) * NEG_BIG;
                    float s1 = sacc[mi][nb][2 + j] * 0.125f + (1.0f - fq[mi][1] * fk) * NEG_BIG;
                    sacc[mi][nb][j] = s0; sacc[mi][nb][2 + j] = s1;
                    mx0 = fmaxf(mx0, s0); mx1 = fmaxf(mx1, s1);
                }
            }
            mx0 = fmaxf(mx0, __shfl_xor_sync(0xffffffffu, mx0, 1));
            mx0 = fmaxf(mx0, __shfl_xor_sync(0xffffffffu, mx0, 2));
            mx1 = fmaxf(mx1, __shfl_xor_sync(0xffffffffu, mx1, 1));
            mx1 = fmaxf(mx1, __shfl_xor_sync(0xffffffffu, mx1, 2));

            float mn0 = fmaxf(mm[mi][0], mx0), mn1 = fmaxf(mm[mi][1], mx1);
            float corr0 = __expf(mm[mi][0] - mn0), corr1 = __expf(mm[mi][1] - mn1);
            mm[mi][0] = mn0; mm[mi][1] = mn1;

            float ls0 = 0.f, ls1 = 0.f;
#pragma unroll
            for (int nb = 0; nb < 8; nb++) {
#pragma unroll
                for (int j = 0; j < 2; j++) {
                    float p0 = __expf(sacc[mi][nb][j] - mn0);
                    float p1 = __expf(sacc[mi][nb][2 + j] - mn1);
                    sacc[mi][nb][j] = p0; sacc[mi][nb][2 + j] = p1;
                    ls0 += p0; ls1 += p1;
                }
            }
            ls0 += __shfl_xor_sync(0xffffffffu, ls0, 1);
            ls0 += __shfl_xor_sync(0xffffffffu, ls0, 2);
            ls1 += __shfl_xor_sync(0xffffffffu, ls1, 1);
            ls1 += __shfl_xor_sync(0xffffffffu, ls1, 2);
            ll[mi][0] = ll[mi][0] * corr0 + ls0;
            ll[mi][1] = ll[mi][1] * corr1 + ls1;
#pragma unroll
            for (int nb = 0; nb < 8; nb++) {
                o[mi][nb][0] *= corr0; o[mi][nb][1] *= corr0;
                o[mi][nb][2] *= corr1; o[mi][nb][3] *= corr1;
            }
        }
        __syncthreads();                    // all warps done reading K

        // stage V tile [key][dim], stride 72, tf32
#pragma unroll
        for (int i = 0; i < 8; i++) {
            int idx = tid + i * 128;
            int r = idx >> 4, cg = idx & 15;
            float4 vv = *(const float4*)&Vb[(size_t)(t * 64 + r) * HD + cg * 4];
            *(uint4*)&sKV[r * VSTR + cg * 4] = tf4(vv);
        }
        __syncthreads();

        // O += P @ V in two 32-key halves (P buffer is per-warp, 32x36)
#pragma unroll
        for (int half = 0; half < 2; half++) {
            // store this half's P (keys half*32 .. half*32+31)
#pragma unroll
            for (int mi = 0; mi < 2; mi++)
#pragma unroll
                for (int nq = 0; nq < 4; nq++) {
                    int nb = half * 4 + nq;
                    *(float2*)&Pw[(mi * 16 + g) * PSTR + nq * 8 + 2 * tig] =
                        make_float2(__uint_as_float(f2tf(sacc[mi][nb][0])),
                                    __uint_as_float(f2tf(sacc[mi][nb][1])));
                    *(float2*)&Pw[(mi * 16 + g + 8) * PSTR + nq * 8 + 2 * tig] =
                        make_float2(__uint_as_float(f2tf(sacc[mi][nb][2])),
                                    __uint_as_float(f2tf(sacc[mi][nb][3])));
                }
            __syncwarp();
#pragma unroll
            for (int kq = 0; kq < 4; kq++) {
                int kc = half * 4 + kq;       // global key chunk
                uint32_t pa[2][4];
#pragma unroll
                for (int mi = 0; mi < 2; mi++) {
                    pa[mi][0] = __float_as_uint(Pw[(mi * 16 + g) * PSTR + kq * 8 + tig]);
                    pa[mi][1] = __float_as_uint(Pw[(mi * 16 + g + 8) * PSTR + kq * 8 + tig]);
                    pa[mi][2] = __float_as_uint(Pw[(mi * 16 + g) * PSTR + kq * 8 + tig + 4]);
                    pa[mi][3] = __float_as_uint(Pw[(mi * 16 + g + 8) * PSTR + kq * 8 + tig + 4]);
                }
#pragma unroll
                for (int nb = 0; nb < 8; nb++) {
                    uint32_t b0 = __float_as_uint(sKV[(kc * 8 + tig)     * VSTR + nb * 8 + g]);
                    uint32_t b1 = __float_as_uint(sKV[(kc * 8 + tig + 4) * VSTR + nb * 8 + g]);
                    mma_tf32(o[0][nb], pa[0], b0, b1);
                    mma_tf32(o[1][nb], pa[1], b0, b1);
                }
            }
            __syncwarp();                    // half-buffer reads done before reuse
        }
    }

    // epilogue: normalize + write [B,S,H*hd]
#pragma unroll
    for (int mi = 0; mi < 2; mi++) {
        float inv0 = 1.0f / ll[mi][0], inv1 = 1.0f / ll[mi][1];
        int row0 = qt * 128 + w * 32 + mi * 16 + g;
#pragma unroll
        for (int nb = 0; nb < 8; nb++) {
            int d = h * HD + nb * 8 + 2 * tig;
            float* dst0 = &out[((size_t)b * SEQ + row0) * HID + d];
            float* dst1 = &out[((size_t)b * SEQ + row0 + 8) * HID + d];
            *(float2*)dst0 = make_float2(o[mi][nb][0] * inv0, o[mi][nb][1] * inv0);
            *(float2*)dst1 = make_float2(o[mi][nb][2] * inv1, o[mi][nb][3] * inv1);
        }
    }
}

// ---------------------------------------------------------------------------
extern "C" void kernel_launch(void* const* d_in, const int* in_sizes, int n_in,
                              void* d_out, int out_size) {
    const float* toks  = (const float*)d_in[0];
    const int*   masks = (const int*)d_in[1];
    const float* Wq = (const float*)d_in[2];
    const float* bq = (const float*)d_in[3];
    const float* Wk = (const float*)d_in[4];
    const float* bk = (const float*)d_in[5];
    const float* Wv = (const float*)d_in[6];
    const float* bv = (const float*)d_in[7];
    float* out = (float*)d_out;

    qkv_gemm_kernel<<<dim3(18, 64), 256>>>(toks, Wq, bq, Wk, bk, Wv, bv);
    attn_kernel<<<dim3(16, NH, BATCH), 128>>>(masks, out);
}

// round 14
// speedup vs baseline: 1.2940x; 1.2940x over previous
#include <cuda_runtime.h>
#include <math.h>
#include <stdint.h>

#define HID   768
#define BATCH 4
#define SEQ   2048
#define NH    12
#define HD    64
#define NEG_BIG (-1e31f)

// Scratch Q,K,V in [B,H,S,hd] layout, stored PRE-CONVERTED to tf32 bit patterns.
__device__ float g_q[BATCH*NH*SEQ*HD];
__device__ float g_k[BATCH*NH*SEQ*HD];
__device__ float g_v[BATCH*NH*SEQ*HD];

// ---------------------------------------------------------------------------
// helpers
// ---------------------------------------------------------------------------
__device__ __forceinline__ uint32_t f2tf(float f) {
    uint32_t u;
    asm("cvt.rna.tf32.f32 %0, %1;" : "=r"(u) : "f"(f));
    return u;
}
__device__ __forceinline__ uint4 tf4(float4 v) {
    uint4 u;
    u.x = f2tf(v.x); u.y = f2tf(v.y); u.z = f2tf(v.z); u.w = f2tf(v.w);
    return u;
}
__device__ __forceinline__ void mma_tf32(float* c, const uint32_t* a,
                                         uint32_t b0, uint32_t b1) {
    asm volatile(
        "mma.sync.aligned.m16n8k8.row.col.f32.tf32.tf32.f32 "
        "{%0,%1,%2,%3},{%4,%5,%6,%7},{%8,%9},{%0,%1,%2,%3};"
        : "+f"(c[0]), "+f"(c[1]), "+f"(c[2]), "+f"(c[3])
        : "r"(a[0]), "r"(a[1]), "r"(a[2]), "r"(a[3]), "r"(b0), "r"(b1));
}
__device__ __forceinline__ uint32_t smem_u32(const void* p) {
    uint32_t a;
    asm("{ .reg .u64 t; cvta.to.shared.u64 t, %1; cvt.u32.u64 %0, t; }"
        : "=r"(a) : "l"(p));
    return a;
}
#define CP16(sa, ga) \
    asm volatile("cp.async.ca.shared.global [%0], [%1], 16;" :: "r"(sa), "l"(ga) : "memory")
#define CP_COMMIT() asm volatile("cp.async.commit_group;" ::: "memory")
#define CP_WAIT_ALL() asm volatile("cp.async.wait_group 0;" ::: "memory")

// ---------------------------------------------------------------------------
// Kernel 1: fused QKV projection, tf32 mma.sync (round-2 design, measured 206us).
// Only change: epilogue stores tf32-rounded values (attention reads them raw).
// ---------------------------------------------------------------------------
#define ASTR 36
#define BSTR 136
__global__ __launch_bounds__(256) void qkv_gemm_kernel(
        const float* __restrict__ toks,
        const float* __restrict__ Wq, const float* __restrict__ bq,
        const float* __restrict__ Wk, const float* __restrict__ bk,
        const float* __restrict__ Wv, const float* __restrict__ bv) {
    __shared__ float sA[128 * ASTR];   // [m][k] stride 36
    __shared__ float sB[32 * BSTR];    // [k][n] stride 136

    const int nbk = blockIdx.x;        // 0..17
    const int mb  = blockIdx.y;        // 0..63
    const int tid = threadIdx.x;
    const int warpId = tid >> 5;
    const int lane = tid & 31;
    const int g   = lane >> 2;
    const int tig = lane & 3;
    const int wm  = warpId >> 1;
    const int wn  = warpId & 1;

    const int w  = (nbk * 128) / HID;
    const int nc = (nbk * 128) % HID;
    const float* __restrict__ Wsel = (w == 0) ? Wq : (w == 1) ? Wk : Wv;
    const float* __restrict__ bsel = (w == 0) ? bq : (w == 1) ? bk : bv;

    float acc[2][8][4];
#pragma unroll
    for (int mi = 0; mi < 2; mi++)
#pragma unroll
        for (int nb = 0; nb < 8; nb++)
#pragma unroll
            for (int j = 0; j < 4; j++) acc[mi][nb][j] = 0.f;

    for (int k0 = 0; k0 < HID; k0 += 32) {
#pragma unroll
        for (int i = 0; i < 4; i++) {
            int idx = tid + i * 256;
            int r = idx >> 3, cg = idx & 7;
            float4 a = *(const float4*)&toks[(size_t)(mb * 128 + r) * HID + k0 + cg * 4];
            *(uint4*)&sA[r * ASTR + cg * 4] = tf4(a);
        }
#pragma unroll
        for (int i = 0; i < 4; i++) {
            int idx = tid + i * 256;
            int r = idx >> 5, cg = idx & 31;
            float4 bvv = *(const float4*)&Wsel[(size_t)(k0 + r) * HID + nc + cg * 4];
            *(uint4*)&sB[r * BSTR + cg * 4] = tf4(bvv);
        }
        __syncthreads();

#pragma unroll
        for (int kc = 0; kc < 4; kc++) {
            uint32_t af[2][4];
#pragma unroll
            for (int mi = 0; mi < 2; mi++) {
                int row = wm * 32 + mi * 16;
                af[mi][0] = __float_as_uint(sA[(row + g)     * ASTR + kc * 8 + tig]);
                af[mi][1] = __float_as_uint(sA[(row + g + 8) * ASTR + kc * 8 + tig]);
                af[mi][2] = __float_as_uint(sA[(row + g)     * ASTR + kc * 8 + tig + 4]);
                af[mi][3] = __float_as_uint(sA[(row + g + 8) * ASTR + kc * 8 + tig + 4]);
            }
            uint32_t bf[8][2];
#pragma unroll
            for (int nb = 0; nb < 8; nb++) {
                int col = wn * 64 + nb * 8 + g;
                bf[nb][0] = __float_as_uint(sB[(kc * 8 + tig)     * BSTR + col]);
                bf[nb][1] = __float_as_uint(sB[(kc * 8 + tig + 4) * BSTR + col]);
            }
#pragma unroll
            for (int mi = 0; mi < 2; mi++)
#pragma unroll
                for (int nb = 0; nb < 8; nb++)
                    mma_tf32(acc[mi][nb], af[mi], bf[nb][0], bf[nb][1]);
        }
        __syncthreads();
    }

    // epilogue: bias, tf32-round, permuted store to [B,H,S,hd]
    float* __restrict__ buf = (w == 0) ? g_q : (w == 1) ? g_k : g_v;
#pragma unroll
    for (int mi = 0; mi < 2; mi++) {
#pragma unroll
        for (int nb = 0; nb < 8; nb++) {
            int n = nc + wn * 64 + nb * 8 + 2 * tig;
            int h = n >> 6;
            int d = n & 63;
            float b0v = bsel[n], b1v = bsel[n + 1];
            int row = mb * 128 + wm * 32 + mi * 16 + g;
            int bb = row >> 11;
            int ss = row & 2047;
            float* dst = &buf[((size_t)(bb * NH + h) * SEQ + ss) * HD + d];
            *(float2*)dst =
                make_float2(__uint_as_float(f2tf(acc[mi][nb][0] + b0v)),
                            __uint_as_float(f2tf(acc[mi][nb][1] + b1v)));
            *(float2*)(dst + 8 * HD) =
                make_float2(__uint_as_float(f2tf(acc[mi][nb][2] + b0v)),
                            __uint_as_float(f2tf(acc[mi][nb][3] + b1v)));
        }
    }
}

// ---------------------------------------------------------------------------
// Kernel 2: flash attention, tf32 mma.sync, round-2 MMA shape (16 q-rows/warp),
// with cp.async staging, K double-buffer prefetch, V end-of-iter prefetch,
// 2 syncthreads/iter (was 4).  Dynamic smem ~69KB, 3 blocks/SM by regs.
// ---------------------------------------------------------------------------
#define KSTR 68
#define VSTR 72
#define PSTR 68
#define ATTN_SMEM ((2 * 64 * KSTR + 64 * VSTR + 4 * 16 * PSTR + 64) * 4)

__global__ __launch_bounds__(128) void attn_kernel(const int* __restrict__ masks,
                                                   float* __restrict__ out) {
    extern __shared__ float smem[];
    float* sK0 = smem;                       // 64*68
    float* sK1 = sK0 + 64 * KSTR;            // 64*68
    float* sV  = sK1 + 64 * KSTR;            // 64*72
    float* sP  = sV  + 64 * VSTR;            // 4*16*68
    float* sMk = sP  + 4 * 16 * PSTR;        // 64

    const int qt  = blockIdx.x;
    const int h   = blockIdx.y;
    const int b   = blockIdx.z;
    const int tid = threadIdx.x;
    const int w    = tid >> 5;
    const int lane = tid & 31;
    const int g    = lane >> 2;
    const int tig  = lane & 3;

    const size_t bh = (size_t)(b * NH + h) * SEQ;
    const float* __restrict__ Qb = g_q + (bh + qt * 64 + w * 16) * HD;
    const float* __restrict__ Kb = g_k + bh * HD;
    const float* __restrict__ Vb = g_v + bh * HD;
    const int*   __restrict__ mrow = masks + b * SEQ;

    const int sr = tid >> 4;                 // staging row (0..63 over 8 iters)
    const int sc = tid & 15;                 // staging col group
    const uint32_t aK[2] = { smem_u32(sK0), smem_u32(sK1) };
    const uint32_t aV    = smem_u32(sV);

    // pre-issue K_0 and V_0
#pragma unroll
    for (int i = 0; i < 8; i++) {
        int r = sr + i * 8;
        CP16(aK[0] + (uint32_t)(r * KSTR + sc * 4) * 4,
             &Kb[(size_t)r * HD + sc * 4]);
    }
#pragma unroll
    for (int i = 0; i < 8; i++) {
        int r = sr + i * 8;
        CP16(aV + (uint32_t)(r * VSTR + sc * 4) * 4,
             &Vb[(size_t)r * HD + sc * 4]);
    }
    CP_COMMIT();

    // Q fragments (already tf32 in g_q) — register resident
    uint32_t qa[8][4];
#pragma unroll
    for (int kc = 0; kc < 8; kc++) {
        qa[kc][0] = __float_as_uint(Qb[(size_t)g * HD + kc * 8 + tig]);
        qa[kc][1] = __float_as_uint(Qb[(size_t)(g + 8) * HD + kc * 8 + tig]);
        qa[kc][2] = __float_as_uint(Qb[(size_t)g * HD + kc * 8 + tig + 4]);
        qa[kc][3] = __float_as_uint(Qb[(size_t)(g + 8) * HD + kc * 8 + tig + 4]);
    }
    const float fq0 = (float)mrow[qt * 64 + w * 16 + g];
    const float fq1 = (float)mrow[qt * 64 + w * 16 + g + 8];

    float o[8][4];
#pragma unroll
    for (int nb = 0; nb < 8; nb++)
#pragma unroll
        for (int j = 0; j < 4; j++) o[nb][j] = 0.f;
    float m0 = -3.0e38f, m1 = -3.0e38f, l0 = 0.f, l1 = 0.f;

    float* Pw = sP + w * 16 * PSTR;

    for (int t = 0; t < SEQ / 64; t++) {
        CP_WAIT_ALL();
        if (tid < 64) sMk[tid] = (float)mrow[t * 64 + tid];
        __syncthreads();                     // K_t, V_t, sMk visible to all

        // prefetch K_{t+1} into the other K buffer (overlaps rest of iter)
        if (t < SEQ / 64 - 1) {
#pragma unroll
            for (int i = 0; i < 8; i++) {
                int r = sr + i * 8;
                CP16(aK[(t + 1) & 1] + (uint32_t)(r * KSTR + sc * 4) * 4,
                     &Kb[(size_t)((t + 1) * 64 + r) * HD + sc * 4]);
            }
            CP_COMMIT();
        }

        const float* __restrict__ Kc = (t & 1) ? sK1 : sK0;

        // S = Q K^T
        float sacc[8][4];
#pragma unroll
        for (int nb = 0; nb < 8; nb++) {
            float c[4] = {0.f, 0.f, 0.f, 0.f};
#pragma unroll
            for (int kc = 0; kc < 8; kc++) {
                uint32_t b0 = __float_as_uint(Kc[(nb * 8 + g) * KSTR + kc * 8 + tig]);
                uint32_t b1 = __float_as_uint(Kc[(nb * 8 + g) * KSTR + kc * 8 + tig + 4]);
                mma_tf32(c, qa[kc], b0, b1);
            }
            sacc[nb][0] = c[0]; sacc[nb][1] = c[1];
            sacc[nb][2] = c[2]; sacc[nb][3] = c[3];
        }

        // scale + mask + online softmax
        float mx0 = -3.0e38f, mx1 = -3.0e38f;
#pragma unroll
        for (int nb = 0; nb < 8; nb++) {
#pragma unroll
            for (int j = 0; j < 2; j++) {
                float fk = sMk[nb * 8 + 2 * tig + j];
                float s0 = sacc[nb][j]     * 0.125f + (1.0f - fq0 * fk) * NEG_BIG;
                float s1 = sacc[nb][2 + j] * 0.125f + (1.0f - fq1 * fk) * NEG_BIG;
                sacc[nb][j] = s0; sacc[nb][2 + j] = s1;
                mx0 = fmaxf(mx0, s0); mx1 = fmaxf(mx1, s1);
            }
        }
        mx0 = fmaxf(mx0, __shfl_xor_sync(0xffffffffu, mx0, 1));
        mx0 = fmaxf(mx0, __shfl_xor_sync(0xffffffffu, mx0, 2));
        mx1 = fmaxf(mx1, __shfl_xor_sync(0xffffffffu, mx1, 1));
        mx1 = fmaxf(mx1, __shfl_xor_sync(0xffffffffu, mx1, 2));

        float mn0 = fmaxf(m0, mx0), mn1 = fmaxf(m1, mx1);
        float corr0 = __expf(m0 - mn0), corr1 = __expf(m1 - mn1);
        m0 = mn0; m1 = mn1;

        float ls0 = 0.f, ls1 = 0.f;
#pragma unroll
        for (int nb = 0; nb < 8; nb++) {
#pragma unroll
            for (int j = 0; j < 2; j++) {
                float p0 = __expf(sacc[nb][j] - m0);
                float p1 = __expf(sacc[nb][2 + j] - m1);
                sacc[nb][j] = p0; sacc[nb][2 + j] = p1;
                ls0 += p0; ls1 += p1;
            }
        }
        ls0 += __shfl_xor_sync(0xffffffffu, ls0, 1);
        ls0 += __shfl_xor_sync(0xffffffffu, ls0, 2);
        ls1 += __shfl_xor_sync(0xffffffffu, ls1, 1);
        ls1 += __shfl_xor_sync(0xffffffffu, ls1, 2);
        l0 = l0 * corr0 + ls0;
        l1 = l1 * corr1 + ls1;
#pragma unroll
        for (int nb = 0; nb < 8; nb++) {
            o[nb][0] *= corr0; o[nb][1] *= corr0;
            o[nb][2] *= corr1; o[nb][3] *= corr1;
        }

        // stage P (warp-private) — __syncwarp ordering only
#pragma unroll
        for (int nb = 0; nb < 8; nb++) {
            *(float2*)&Pw[g * PSTR + nb * 8 + 2 * tig] =
                make_float2(__uint_as_float(f2tf(sacc[nb][0])),
                            __uint_as_float(f2tf(sacc[nb][1])));
            *(float2*)&Pw[(g + 8) * PSTR + nb * 8 + 2 * tig] =
                make_float2(__uint_as_float(f2tf(sacc[nb][2])),
                            __uint_as_float(f2tf(sacc[nb][3])));
        }
        __syncwarp();

        // O += P @ V  (V_t already resident in sV)
#pragma unroll
        for (int kc = 0; kc < 8; kc++) {
            uint32_t pa[4];
            pa[0] = __float_as_uint(Pw[g * PSTR + kc * 8 + tig]);
            pa[1] = __float_as_uint(Pw[(g + 8) * PSTR + kc * 8 + tig]);
            pa[2] = __float_as_uint(Pw[g * PSTR + kc * 8 + tig + 4]);
            pa[3] = __float_as_uint(Pw[(g + 8) * PSTR + kc * 8 + tig + 4]);
#pragma unroll
            for (int nb = 0; nb < 8; nb++) {
                uint32_t b0 = __float_as_uint(sV[(kc * 8 + tig)     * VSTR + nb * 8 + g]);
                uint32_t b1 = __float_as_uint(sV[(kc * 8 + tig + 4) * VSTR + nb * 8 + g]);
                mma_tf32(o[nb], pa, b0, b1);
            }
        }
        __syncthreads();                     // all warps done with V_t (and K_t)

        // prefetch V_{t+1} (single buffer, safe after sync)
        if (t < SEQ / 64 - 1) {
#pragma unroll
            for (int i = 0; i < 8; i++) {
                int r = sr + i * 8;
                CP16(aV + (uint32_t)(r * VSTR + sc * 4) * 4,
                     &Vb[(size_t)((t + 1) * 64 + r) * HD + sc * 4]);
            }
            CP_COMMIT();
        }
    }

    // epilogue: normalize + write [B,S,H*hd]
    float inv0 = 1.0f / l0, inv1 = 1.0f / l1;
    int row0 = qt * 64 + w * 16 + g;
#pragma unroll
    for (int nb = 0; nb < 8; nb++) {
        int d = h * HD + nb * 8 + 2 * tig;
        float* dst0 = &out[((size_t)b * SEQ + row0) * HID + d];
        float* dst1 = &out[((size_t)b * SEQ + row0 + 8) * HID + d];
        *(float2*)dst0 = make_float2(o[nb][0] * inv0, o[nb][1] * inv0);
        *(float2*)dst1 = make_float2(o[nb][2] * inv1, o[nb][3] * inv1);
    }
}

// ---------------------------------------------------------------------------
extern "C" void kernel_launch(void* const* d_in, const int* in_sizes, int n_in,
                              void* d_out, int out_size) {
    const float* toks  = (const float*)d_in[0];
    const int*   masks = (const int*)d_in[1];
    const float* Wq = (const float*)d_in[2];
    const float* bq = (const float*)d_in[3];
    const float* Wk = (const float*)d_in[4];
    const float* bk = (const float*)d_in[5];
    const float* Wv = (const float*)d_in[6];
    const float* bv = (const float*)d_in[7];
    float* out = (float*)d_out;

    cudaFuncSetAttribute(attn_kernel, cudaFuncAttributeMaxDynamicSharedMemorySize,
                         ATTN_SMEM);

    qkv_gemm_kernel<<<dim3(18, 64), 256>>>(toks, Wq, bq, Wk, bk, Wv, bv);
    attn_kernel<<<dim3(32, NH, BATCH), 128, ATTN_SMEM>>>(masks, out);
}

// round 15
// speedup vs baseline: 1.3490x; 1.0425x over previous
#include <cuda_runtime.h>
#include <math.h>
#include <stdint.h>

#define HID   768
#define BATCH 4
#define SEQ   2048
#define NH    12
#define HD    64
#define NEG_BIG (-1e31f)

// Scratch Q,K,V in [B,H,S,hd] layout, stored PRE-CONVERTED to tf32 bit patterns.
__device__ float g_q[BATCH*NH*SEQ*HD];
__device__ float g_k[BATCH*NH*SEQ*HD];
__device__ float g_v[BATCH*NH*SEQ*HD];

// ---------------------------------------------------------------------------
// helpers
// ---------------------------------------------------------------------------
__device__ __forceinline__ uint32_t f2tf(float f) {
    uint32_t u;
    asm("cvt.rna.tf32.f32 %0, %1;" : "=r"(u) : "f"(f));
    return u;
}
__device__ __forceinline__ uint4 tf4(float4 v) {
    uint4 u;
    u.x = f2tf(v.x); u.y = f2tf(v.y); u.z = f2tf(v.z); u.w = f2tf(v.w);
    return u;
}
__device__ __forceinline__ void mma_tf32(float* c, const uint32_t* a,
                                         uint32_t b0, uint32_t b1) {
    asm volatile(
        "mma.sync.aligned.m16n8k8.row.col.f32.tf32.tf32.f32 "
        "{%0,%1,%2,%3},{%4,%5,%6,%7},{%8,%9},{%0,%1,%2,%3};"
        : "+f"(c[0]), "+f"(c[1]), "+f"(c[2]), "+f"(c[3])
        : "r"(a[0]), "r"(a[1]), "r"(a[2]), "r"(a[3]), "r"(b0), "r"(b1));
}
__device__ __forceinline__ uint32_t smem_u32(const void* p) {
    uint32_t a;
    asm("{ .reg .u64 t; cvta.to.shared.u64 t, %1; cvt.u32.u64 %0, t; }"
        : "=r"(a) : "l"(p));
    return a;
}
#define CP16(sa, ga) \
    asm volatile("cp.async.ca.shared.global [%0], [%1], 16;" :: "r"(sa), "l"(ga) : "memory")
#define CP_COMMIT() asm volatile("cp.async.commit_group;" ::: "memory")
#define CP_WAIT1()  asm volatile("cp.async.wait_group 1;" ::: "memory")
#define CP_WAIT0()  asm volatile("cp.async.wait_group 0;" ::: "memory")

// ---------------------------------------------------------------------------
// Kernel 1: fused QKV projection, tf32 mma.sync (measured ~202us, unchanged).
// Epilogue stores tf32-rounded values (attention reads them raw).
// ---------------------------------------------------------------------------
#define ASTR 36
#define BSTR 136
__global__ __launch_bounds__(256) void qkv_gemm_kernel(
        const float* __restrict__ toks,
        const float* __restrict__ Wq, const float* __restrict__ bq,
        const float* __restrict__ Wk, const float* __restrict__ bk,
        const float* __restrict__ Wv, const float* __restrict__ bv) {
    __shared__ float sA[128 * ASTR];   // [m][k] stride 36
    __shared__ float sB[32 * BSTR];    // [k][n] stride 136

    const int nbk = blockIdx.x;        // 0..17
    const int mb  = blockIdx.y;        // 0..63
    const int tid = threadIdx.x;
    const int warpId = tid >> 5;
    const int lane = tid & 31;
    const int g   = lane >> 2;
    const int tig = lane & 3;
    const int wm  = warpId >> 1;
    const int wn  = warpId & 1;

    const int w  = (nbk * 128) / HID;
    const int nc = (nbk * 128) % HID;
    const float* __restrict__ Wsel = (w == 0) ? Wq : (w == 1) ? Wk : Wv;
    const float* __restrict__ bsel = (w == 0) ? bq : (w == 1) ? bk : bv;

    float acc[2][8][4];
#pragma unroll
    for (int mi = 0; mi < 2; mi++)
#pragma unroll
        for (int nb = 0; nb < 8; nb++)
#pragma unroll
            for (int j = 0; j < 4; j++) acc[mi][nb][j] = 0.f;

    for (int k0 = 0; k0 < HID; k0 += 32) {
#pragma unroll
        for (int i = 0; i < 4; i++) {
            int idx = tid + i * 256;
            int r = idx >> 3, cg = idx & 7;
            float4 a = *(const float4*)&toks[(size_t)(mb * 128 + r) * HID + k0 + cg * 4];
            *(uint4*)&sA[r * ASTR + cg * 4] = tf4(a);
        }
#pragma unroll
        for (int i = 0; i < 4; i++) {
            int idx = tid + i * 256;
            int r = idx >> 5, cg = idx & 31;
            float4 bvv = *(const float4*)&Wsel[(size_t)(k0 + r) * HID + nc + cg * 4];
            *(uint4*)&sB[r * BSTR + cg * 4] = tf4(bvv);
        }
        __syncthreads();

#pragma unroll
        for (int kc = 0; kc < 4; kc++) {
            uint32_t af[2][4];
#pragma unroll
            for (int mi = 0; mi < 2; mi++) {
                int row = wm * 32 + mi * 16;
                af[mi][0] = __float_as_uint(sA[(row + g)     * ASTR + kc * 8 + tig]);
                af[mi][1] = __float_as_uint(sA[(row + g + 8) * ASTR + kc * 8 + tig]);
                af[mi][2] = __float_as_uint(sA[(row + g)     * ASTR + kc * 8 + tig + 4]);
                af[mi][3] = __float_as_uint(sA[(row + g + 8) * ASTR + kc * 8 + tig + 4]);
            }
            uint32_t bf[8][2];
#pragma unroll
            for (int nb = 0; nb < 8; nb++) {
                int col = wn * 64 + nb * 8 + g;
                bf[nb][0] = __float_as_uint(sB[(kc * 8 + tig)     * BSTR + col]);
                bf[nb][1] = __float_as_uint(sB[(kc * 8 + tig + 4) * BSTR + col]);
            }
#pragma unroll
            for (int mi = 0; mi < 2; mi++)
#pragma unroll
                for (int nb = 0; nb < 8; nb++)
                    mma_tf32(acc[mi][nb], af[mi], bf[nb][0], bf[nb][1]);
        }
        __syncthreads();
    }

    float* __restrict__ buf = (w == 0) ? g_q : (w == 1) ? g_k : g_v;
#pragma unroll
    for (int mi = 0; mi < 2; mi++) {
#pragma unroll
        for (int nb = 0; nb < 8; nb++) {
            int n = nc + wn * 64 + nb * 8 + 2 * tig;
            int h = n >> 6;
            int d = n & 63;
            float b0v = bsel[n], b1v = bsel[n + 1];
            int row = mb * 128 + wm * 32 + mi * 16 + g;
            int bb = row >> 11;
            int ss = row & 2047;
            float* dst = &buf[((size_t)(bb * NH + h) * SEQ + ss) * HD + d];
            *(float2*)dst =
                make_float2(__uint_as_float(f2tf(acc[mi][nb][0] + b0v)),
                            __uint_as_float(f2tf(acc[mi][nb][1] + b1v)));
            *(float2*)(dst + 8 * HD) =
                make_float2(__uint_as_float(f2tf(acc[mi][nb][2] + b0v)),
                            __uint_as_float(f2tf(acc[mi][nb][3] + b1v)));
        }
    }
}

// ---------------------------------------------------------------------------
// Kernel 2: flash attention, tf32 mma.sync, 16 q-rows/warp, SINGLE K and V
// buffers (52.3KB smem -> 4 blocks/SM) with full prefetch overlap via
// in-order cp.async group completion + staged wait_group 1:
//   issue K_{t+1} after QK^T reads K_t   (overlaps softmax+PV of t)
//   issue V_{t+1} after PV reads V_t     (overlaps QK^T+softmax of t+1)
// ---------------------------------------------------------------------------
#define KSTR 68
#define VSTR 72
#define PSTR 68
#define ATTN_SMEM ((64 * KSTR + 64 * VSTR + 4 * 16 * PSTR + 64) * 4)

__global__ __launch_bounds__(128) void attn_kernel(const int* __restrict__ masks,
                                                   float* __restrict__ out) {
    extern __shared__ float smem[];
    float* sK  = smem;                       // 64*68
    float* sV  = sK + 64 * KSTR;             // 64*72
    float* sP  = sV + 64 * VSTR;             // 4*16*68
    float* sMk = sP + 4 * 16 * PSTR;         // 64

    const int qt  = blockIdx.x;
    const int h   = blockIdx.y;
    const int b   = blockIdx.z;
    const int tid = threadIdx.x;
    const int w    = tid >> 5;
    const int lane = tid & 31;
    const int g    = lane >> 2;
    const int tig  = lane & 3;

    const size_t bh = (size_t)(b * NH + h) * SEQ;
    const float* __restrict__ Qb = g_q + (bh + qt * 64 + w * 16) * HD;
    const float* __restrict__ Kb = g_k + bh * HD;
    const float* __restrict__ Vb = g_v + bh * HD;
    const int*   __restrict__ mrow = masks + b * SEQ;

    const int sr = tid >> 4;                 // staging row base (0..7)
    const int sc = tid & 15;                 // staging col group
    const uint32_t aK = smem_u32(sK);
    const uint32_t aV = smem_u32(sV);

    // pre-issue K_0 (group 0) then V_0 (group 1)
#pragma unroll
    for (int i = 0; i < 8; i++) {
        int r = sr + i * 8;
        CP16(aK + (uint32_t)(r * KSTR + sc * 4) * 4, &Kb[(size_t)r * HD + sc * 4]);
    }
    CP_COMMIT();
#pragma unroll
    for (int i = 0; i < 8; i++) {
        int r = sr + i * 8;
        CP16(aV + (uint32_t)(r * VSTR + sc * 4) * 4, &Vb[(size_t)r * HD + sc * 4]);
    }
    CP_COMMIT();

    // Q fragments (already tf32 in g_q) — register resident
    uint32_t qa[8][4];
#pragma unroll
    for (int kc = 0; kc < 8; kc++) {
        qa[kc][0] = __float_as_uint(Qb[(size_t)g * HD + kc * 8 + tig]);
        qa[kc][1] = __float_as_uint(Qb[(size_t)(g + 8) * HD + kc * 8 + tig]);
        qa[kc][2] = __float_as_uint(Qb[(size_t)g * HD + kc * 8 + tig + 4]);
        qa[kc][3] = __float_as_uint(Qb[(size_t)(g + 8) * HD + kc * 8 + tig + 4]);
    }
    const float fq0 = (float)mrow[qt * 64 + w * 16 + g];
    const float fq1 = (float)mrow[qt * 64 + w * 16 + g + 8];

    float o[8][4];
#pragma unroll
    for (int nb = 0; nb < 8; nb++)
#pragma unroll
        for (int j = 0; j < 4; j++) o[nb][j] = 0.f;
    float m0 = -3.0e38f, m1 = -3.0e38f, l0 = 0.f, l1 = 0.f;

    float* Pw = sP + w * 16 * PSTR;
    const int NT = SEQ / 64;

    for (int t = 0; t < NT; t++) {
        // K_t is the oldest pending group -> wait_group 1 completes it
        CP_WAIT1();
        if (tid < 64) sMk[tid] = (float)mrow[t * 64 + tid];
        __syncthreads();                     // K_t + sMk visible to all warps

        // S = Q K^T
        float sacc[8][4];
#pragma unroll
        for (int nb = 0; nb < 8; nb++) {
            float c[4] = {0.f, 0.f, 0.f, 0.f};
#pragma unroll
            for (int kc = 0; kc < 8; kc++) {
                uint32_t b0 = __float_as_uint(sK[(nb * 8 + g) * KSTR + kc * 8 + tig]);
                uint32_t b1 = __float_as_uint(sK[(nb * 8 + g) * KSTR + kc * 8 + tig + 4]);
                mma_tf32(c, qa[kc], b0, b1);
            }
            sacc[nb][0] = c[0]; sacc[nb][1] = c[1];
            sacc[nb][2] = c[2]; sacc[nb][3] = c[3];
        }
        __syncthreads();                     // all warps done reading K_t

        // issue K_{t+1} into the (now free) K buffer — overlaps softmax + PV
        if (t + 1 < NT) {
#pragma unroll
            for (int i = 0; i < 8; i++) {
                int r = sr + i * 8;
                CP16(aK + (uint32_t)(r * KSTR + sc * 4) * 4,
                     &Kb[(size_t)((t + 1) * 64 + r) * HD + sc * 4]);
            }
            CP_COMMIT();
        }

        // scale + mask + online softmax
        float mx0 = -3.0e38f, mx1 = -3.0e38f;
#pragma unroll
        for (int nb = 0; nb < 8; nb++) {
#pragma unroll
            for (int j = 0; j < 2; j++) {
                float fk = sMk[nb * 8 + 2 * tig + j];
                float s0 = sacc[nb][j]     * 0.125f + (1.0f - fq0 * fk) * NEG_BIG;
                float s1 = sacc[nb][2 + j] * 0.125f + (1.0f - fq1 * fk) * NEG_BIG;
                sacc[nb][j] = s0; sacc[nb][2 + j] = s1;
                mx0 = fmaxf(mx0, s0); mx1 = fmaxf(mx1, s1);
            }
        }
        mx0 = fmaxf(mx0, __shfl_xor_sync(0xffffffffu, mx0, 1));
        mx0 = fmaxf(mx0, __shfl_xor_sync(0xffffffffu, mx0, 2));
        mx1 = fmaxf(mx1, __shfl_xor_sync(0xffffffffu, mx1, 1));
        mx1 = fmaxf(mx1, __shfl_xor_sync(0xffffffffu, mx1, 2));

        float mn0 = fmaxf(m0, mx0), mn1 = fmaxf(m1, mx1);
        float corr0 = __expf(m0 - mn0), corr1 = __expf(m1 - mn1);
        m0 = mn0; m1 = mn1;

        float ls0 = 0.f, ls1 = 0.f;
#pragma unroll
        for (int nb = 0; nb < 8; nb++) {
#pragma unroll
            for (int j = 0; j < 2; j++) {
                float p0 = __expf(sacc[nb][j] - m0);
                float p1 = __expf(sacc[nb][2 + j] - m1);
                sacc[nb][j] = p0; sacc[nb][2 + j] = p1;
                ls0 += p0; ls1 += p1;
            }
        }
        ls0 += __shfl_xor_sync(0xffffffffu, ls0, 1);
        ls0 += __shfl_xor_sync(0xffffffffu, ls0, 2);
        ls1 += __shfl_xor_sync(0xffffffffu, ls1, 1);
        ls1 += __shfl_xor_sync(0xffffffffu, ls1, 2);
        l0 = l0 * corr0 + ls0;
        l1 = l1 * corr1 + ls1;
#pragma unroll
        for (int nb = 0; nb < 8; nb++) {
            o[nb][0] *= corr0; o[nb][1] *= corr0;
            o[nb][2] *= corr1; o[nb][3] *= corr1;
        }

        // stage P (warp-private)
#pragma unroll
        for (int nb = 0; nb < 8; nb++) {
            *(float2*)&Pw[g * PSTR + nb * 8 + 2 * tig] =
                make_float2(__uint_as_float(f2tf(sacc[nb][0])),
                            __uint_as_float(f2tf(sacc[nb][1])));
            *(float2*)&Pw[(g + 8) * PSTR + nb * 8 + 2 * tig] =
                make_float2(__uint_as_float(f2tf(sacc[nb][2])),
                            __uint_as_float(f2tf(sacc[nb][3])));
        }
        __syncwarp();

        // V_t is now the oldest pending group (K_{t+1} newer) -> wait_group 1
        CP_WAIT1();
        __syncthreads();                     // V_t visible to all warps

        // O += P @ V
#pragma unroll
        for (int kc = 0; kc < 8; kc++) {
            uint32_t pa[4];
            pa[0] = __float_as_uint(Pw[g * PSTR + kc * 8 + tig]);
            pa[1] = __float_as_uint(Pw[(g + 8) * PSTR + kc * 8 + tig]);
            pa[2] = __float_as_uint(Pw[g * PSTR + kc * 8 + tig + 4]);
            pa[3] = __float_as_uint(Pw[(g + 8) * PSTR + kc * 8 + tig + 4]);
#pragma unroll
            for (int nb = 0; nb < 8; nb++) {
                uint32_t b0 = __float_as_uint(sV[(kc * 8 + tig)     * VSTR + nb * 8 + g]);
                uint32_t b1 = __float_as_uint(sV[(kc * 8 + tig + 4) * VSTR + nb * 8 + g]);
                mma_tf32(o[nb], pa, b0, b1);
            }
        }
        __syncthreads();                     // all warps done reading V_t

        // issue V_{t+1} — overlaps QK^T + softmax of iter t+1
        if (t + 1 < NT) {
#pragma unroll
            for (int i = 0; i < 8; i++) {
                int r = sr + i * 8;
                CP16(aV + (uint32_t)(r * VSTR + sc * 4) * 4,
                     &Vb[(size_t)((t + 1) * 64 + r) * HD + sc * 4]);
            }
            CP_COMMIT();
        }
    }
    CP_WAIT0();

    // epilogue: normalize + write [B,S,H*hd]
    float inv0 = 1.0f / l0, inv1 = 1.0f / l1;
    int row0 = qt * 64 + w * 16 + g;
#pragma unroll
    for (int nb = 0; nb < 8; nb++) {
        int d = h * HD + nb * 8 + 2 * tig;
        float* dst0 = &out[((size_t)b * SEQ + row0) * HID + d];
        float* dst1 = &out[((size_t)b * SEQ + row0 + 8) * HID + d];
        *(float2*)dst0 = make_float2(o[nb][0] * inv0, o[nb][1] * inv0);
        *(float2*)dst1 = make_float2(o[nb][2] * inv1, o[nb][3] * inv1);
    }
}

// ---------------------------------------------------------------------------
extern "C" void kernel_launch(void* const* d_in, const int* in_sizes, int n_in,
                              void* d_out, int out_size) {
    const float* toks  = (const float*)d_in[0];
    const int*   masks = (const int*)d_in[1];
    const float* Wq = (const float*)d_in[2];
    const float* bq = (const float*)d_in[3];
    const float* Wk = (const float*)d_in[4];
    const float* bk = (const float*)d_in[5];
    const float* Wv = (const float*)d_in[6];
    const float* bv = (const float*)d_in[7];
    float* out = (float*)d_out;

    cudaFuncSetAttribute(attn_kernel, cudaFuncAttributeMaxDynamicSharedMemorySize,
                         ATTN_SMEM);

    qkv_gemm_kernel<<<dim3(18, 64), 256>>>(toks, Wq, bq, Wk, bk, Wv, bv);
    attn_kernel<<<dim3(32, NH, BATCH), 128, ATTN_SMEM>>>(masks, out);
}